// round 10
// baseline (speedup 1.0000x reference)
#include <cuda_runtime.h>

#define NTOT      40
#define NX        20
#define BATCHN    524288
#define TPB       320                 // 32 rows * 10 float4-chunks per row
#define ROWS_TILE 32
#define ITERS     4
#define ROWS_BLOCK (ROWS_TILE * ITERS)       // 128 rows per block
#define NBLOCKS   (BATCHN / ROWS_BLOCK)      // 4096

// Per-block double partials (each block writes its own slot every launch).
__device__ double g_part_dd[NBLOCKS];
__device__ double g_part_pi[NBLOCKS];
__device__ unsigned int g_ticket = 0;   // re-armed to 0 by the last block

// Release+acquire ticket WITHOUT __threadfence: gpu-scope fence would emit
// CCTL.IVALL (full L1D flush) per block — the measured ~8us fusion penalty in
// earlier rounds. atom.acq_rel orders this thread's prior global stores
// (release) and makes all other blocks' released stores visible to the last
// arriver (acquire), with no L1 invalidate.
__device__ __forceinline__ unsigned int ticketAcqRel(unsigned int* p)
{
    unsigned int old;
    asm volatile("atom.acq_rel.gpu.global.add.u32 %0, [%1], %2;"
                 : "=r"(old) : "l"(p), "r"(1u) : "memory");
    return old;
}

__global__ __launch_bounds__(TPB) void hybrid_loss_kernel(
    const float* __restrict__ pred,
    const float* __restrict__ targ,
    const float* __restrict__ ycur,
    float* __restrict__ out)
{
    __shared__ __align__(16) float sp[ROWS_TILE][44];   // 44-stride pad, 16B rows

    const int t = threadIdx.x;
    const int r = t / 10;           // row within tile (0..31)
    const int j = t - r * 10;       // float4 chunk within row (0..9)

    const float4* __restrict__ p4 = (const float4*)pred;
    const float4* __restrict__ y4 = (const float4*)ycur;
    const float2* __restrict__ t2 = (const float2*)targ;

    const int base_row = blockIdx.x * ROWS_BLOCK;

    float acc_dd = 0.0f;
    float acc_pi = 0.0f;

    // Prefetch iteration 0 (pred/y coalesced float4; targ float2 over observed cols)
    float4 pv = p4[base_row * 10 + t];
    float4 yv = y4[base_row * 10 + t];
    float2 tv = t2[(base_row + r) * 20 + j];

    // Stencil neighbor indices within the 40-wide row (periodic wrap).
    const int i0  = 4 * j;
    const int im2 = (j == 0) ? 38 : i0 - 2;
    const int im1 = (j == 0) ? 39 : i0 - 1;
    const int ip1 = (j == 9) ? 0  : i0 + 4;

    #pragma unroll
    for (int it = 0; it < ITERS; ++it) {
        float4 pc = pv;
        float4 yc = yv;
        float2 tc = tv;

        // Prefetch next tile before the barrier — LDG latency overlaps barrier+compute.
        if (it + 1 < ITERS) {
            int nb = base_row + (it + 1) * ROWS_TILE;
            pv = p4[nb * 10 + t];
            yv = y4[nb * 10 + t];
            tv = t2[(nb + r) * 20 + j];
        }

        // Stage pred tile (float4 store: row stride 176B, 16B aligned).
        *reinterpret_cast<float4*>(&sp[r][i0]) = pc;
        __syncthreads();

        // ---- data-driven term: elements 2j, 2j+1 of row r (cols 0..19) ----
        {
            float d0 = sp[r][2 * j]     - tc.x;
            float d1 = sp[r][2 * j + 1] - tc.y;
            acc_dd += d0 * d0 + d1 * d1;
        }

        // ---- physics term: Lorenz-96 RHS with periodic wrap ----
        {
            float pm2 = sp[r][im2];
            float pm1 = sp[r][im1];
            float pp1 = sp[r][ip1];
            float p0 = pc.x, p1 = pc.y, p2 = pc.z, p3 = pc.w;

            float f0 = (p1  - pm2) * pm1 - p0 + 8.0f;
            float f1 = (p2  - pm1) * p0  - p1 + 8.0f;
            float f2 = (p3  - p0 ) * p1  - p2 + 8.0f;
            float f3 = (pp1 - p1 ) * p2  - p3 + 8.0f;

            float d0 = (p0 - yc.x) * 100.0f - f0;
            float d1 = (p1 - yc.y) * 100.0f - f1;
            float d2 = (p2 - yc.z) * 100.0f - f2;
            float d3 = (p3 - yc.w) * 100.0f - f3;

            acc_pi += d0 * d0 + d1 * d1 + d2 * d2 + d3 * d3;
        }
        __syncthreads();   // protect smem before next iteration's store
    }

    // ---- block reduction: warp shuffle (float) -> smem (double) ----
    #pragma unroll
    for (int o = 16; o; o >>= 1) {
        acc_dd += __shfl_xor_sync(0xFFFFFFFFu, acc_dd, o);
        acc_pi += __shfl_xor_sync(0xFFFFFFFFu, acc_pi, o);
    }
    __shared__ double wdd[TPB / 32], wpi[TPB / 32];
    __shared__ int s_last;
    const int lane = t & 31, w = t >> 5;
    if (lane == 0) { wdd[w] = (double)acc_dd; wpi[w] = (double)acc_pi; }
    __syncthreads();
    if (t == 0) {
        double a = 0.0, b = 0.0;
        #pragma unroll
        for (int i = 0; i < TPB / 32; ++i) { a += wdd[i]; b += wpi[i]; }
        g_part_dd[blockIdx.x] = a;
        g_part_pi[blockIdx.x] = b;
        // Release-ordered ticket (no L1 flush). Last arriver sees all partials.
        unsigned int v = ticketAcqRel(&g_ticket);
        s_last = (v == (unsigned int)(gridDim.x - 1));
    }
    __syncthreads();

    // ---- last block: final reduction in fixed order (deterministic) ----
    if (s_last) {
        double a = 0.0, b = 0.0;
        // __ldcg: read via L2 (partials were released there; bypass any L1 state).
        for (int k = t; k < NBLOCKS; k += TPB) {
            a += __ldcg(&g_part_dd[k]);
            b += __ldcg(&g_part_pi[k]);
        }
        #pragma unroll
        for (int o = 16; o; o >>= 1) {
            a += __shfl_xor_sync(0xFFFFFFFFu, a, o);
            b += __shfl_xor_sync(0xFFFFFFFFu, b, o);
        }
        if (lane == 0) { wdd[w] = a; wpi[w] = b; }
        __syncthreads();
        if (t == 0) {
            double A = 0.0, B = 0.0;
            #pragma unroll
            for (int i = 0; i < TPB / 32; ++i) { A += wdd[i]; B += wpi[i]; }
            double l_dd = A / ((double)BATCHN * (double)NX);
            double l_pi = B / ((double)BATCHN * (double)NTOT);
            out[0] = (float)(l_dd + 0.1 * l_pi);   // total_loss
            out[1] = (float)l_dd;
            out[2] = (float)l_pi;
            g_ticket = 0;   // re-arm for next graph replay (launch boundary orders this)
        }
    }
}

extern "C" void kernel_launch(void* const* d_in, const int* in_sizes, int n_in,
                              void* d_out, int out_size)
{
    const float* pred = (const float*)d_in[0];   // predictions [524288, 40]
    const float* targ = (const float*)d_in[1];   // targets     [524288, 40]
    const float* ycur = (const float*)d_in[2];   // y_current   [524288, 40]
    float* out = (float*)d_out;                  // [total, l_dd, l_pi]

    hybrid_loss_kernel<<<NBLOCKS, TPB>>>(pred, targ, ycur, out);
}

// round 11
// speedup vs baseline: 1.2073x; 1.2073x over previous
#include <cuda_runtime.h>

#define NTOT      40
#define NX        20
#define BATCHN    524288
#define TPB       320                 // 32 rows * 10 float4-chunks per row
#define ROWS_TILE 32
#define ITERS     4
#define ROWS_BLOCK (ROWS_TILE * ITERS)       // 128 rows per block
#define NBLOCKS   (BATCHN / ROWS_BLOCK)      // 4096

#define FIN_GRID  148                 // >=148 blocks: dodge single-CTA issue throttle
#define FIN_TPB   256

// Per-block double partials (each block writes its own slot every launch).
__device__ double g_part_dd[NBLOCKS];
__device__ double g_part_pi[NBLOCKS];

__global__ __launch_bounds__(TPB) void hybrid_loss_kernel(
    const float* __restrict__ pred,
    const float* __restrict__ targ,
    const float* __restrict__ ycur)
{
    __shared__ __align__(16) float sp[ROWS_TILE][44];   // 44-stride pad, 16B-aligned rows

    const int t = threadIdx.x;
    const int r = t / 10;           // row within tile (0..31)
    const int j = t - r * 10;       // float4 chunk within row (0..9)

    const float4* __restrict__ p4 = (const float4*)pred;
    const float4* __restrict__ y4 = (const float4*)ycur;
    const float2* __restrict__ t2 = (const float2*)targ;

    const int base_row = blockIdx.x * ROWS_BLOCK;

    float acc_dd = 0.0f;
    float acc_pi = 0.0f;

    // Prefetch iteration 0 (pred/y fully coalesced float4; targ float2 over observed cols)
    float4 pv = p4[base_row * 10 + t];
    float4 yv = y4[base_row * 10 + t];
    float2 tv = t2[(base_row + r) * 20 + j];

    // Stencil neighbor indices within the 40-wide row (periodic wrap).
    const int i0  = 4 * j;
    const int im2 = (j == 0) ? 38 : i0 - 2;
    const int im1 = (j == 0) ? 39 : i0 - 1;
    const int ip1 = (j == 9) ? 0  : i0 + 4;

    #pragma unroll
    for (int it = 0; it < ITERS; ++it) {
        float4 pc = pv;
        float4 yc = yv;
        float2 tc = tv;

        // Prefetch next tile before the barrier — LDG latency overlaps barrier+compute.
        if (it + 1 < ITERS) {
            int nb = base_row + (it + 1) * ROWS_TILE;
            pv = p4[nb * 10 + t];
            yv = y4[nb * 10 + t];
            tv = t2[(nb + r) * 20 + j];
        }

        // Stage pred tile (float4 store: row stride 176B, 16B aligned).
        *reinterpret_cast<float4*>(&sp[r][i0]) = pc;
        __syncthreads();

        // ---- data-driven term: elements 2j, 2j+1 of row r (cols 0..19) ----
        {
            float d0 = sp[r][2 * j]     - tc.x;
            float d1 = sp[r][2 * j + 1] - tc.y;
            acc_dd += d0 * d0 + d1 * d1;
        }

        // ---- physics term: Lorenz-96 RHS with periodic wrap ----
        {
            float pm2 = sp[r][im2];
            float pm1 = sp[r][im1];
            float pp1 = sp[r][ip1];
            float p0 = pc.x, p1 = pc.y, p2 = pc.z, p3 = pc.w;

            float f0 = (p1  - pm2) * pm1 - p0 + 8.0f;
            float f1 = (p2  - pm1) * p0  - p1 + 8.0f;
            float f2 = (p3  - p0 ) * p1  - p2 + 8.0f;
            float f3 = (pp1 - p1 ) * p2  - p3 + 8.0f;

            float d0 = (p0 - yc.x) * 100.0f - f0;
            float d1 = (p1 - yc.y) * 100.0f - f1;
            float d2 = (p2 - yc.z) * 100.0f - f2;
            float d3 = (p3 - yc.w) * 100.0f - f3;

            acc_pi += d0 * d0 + d1 * d1 + d2 * d2 + d3 * d3;
        }
        __syncthreads();   // protect smem before next iteration's store
    }

    // ---- block reduction: warp shuffle (float) -> smem (double) -> one write ----
    #pragma unroll
    for (int o = 16; o; o >>= 1) {
        acc_dd += __shfl_xor_sync(0xFFFFFFFFu, acc_dd, o);
        acc_pi += __shfl_xor_sync(0xFFFFFFFFu, acc_pi, o);
    }
    __shared__ double wdd[TPB / 32], wpi[TPB / 32];
    int lane = t & 31, w = t >> 5;
    if (lane == 0) { wdd[w] = (double)acc_dd; wpi[w] = (double)acc_pi; }
    __syncthreads();
    if (t == 0) {
        double a = 0.0, b = 0.0;
        #pragma unroll
        for (int i = 0; i < TPB / 32; ++i) { a += wdd[i]; b += wpi[i]; }
        g_part_dd[blockIdx.x] = a;
        g_part_pi[blockIdx.x] = b;
    }
}

// grid=148: the sm_103a single-CTA issue throttle (~x38, vanishes @grid>=148)
// is what made 1-block finalize cost 10-12us regardless of MLP. All blocks
// redundantly compute the same fixed-order reduction (64KB broadcast from L2);
// only block 0 writes the outputs -> deterministic.
__global__ __launch_bounds__(FIN_TPB) void finalize_kernel(float* __restrict__ out)
{
    const int t = threadIdx.x;

    double a = 0.0, b = 0.0;
    #pragma unroll
    for (int i = 0; i < NBLOCKS / FIN_TPB; ++i) {     // 16 iterations
        a += g_part_dd[t + i * FIN_TPB];
        b += g_part_pi[t + i * FIN_TPB];
    }

    #pragma unroll
    for (int o = 16; o; o >>= 1) {
        a += __shfl_xor_sync(0xFFFFFFFFu, a, o);
        b += __shfl_xor_sync(0xFFFFFFFFu, b, o);
    }
    __shared__ double sa[FIN_TPB / 32], sb[FIN_TPB / 32];
    int lane = t & 31, w = t >> 5;
    if (lane == 0) { sa[w] = a; sb[w] = b; }
    __syncthreads();
    if (blockIdx.x == 0 && t == 0) {
        double A = 0.0, B = 0.0;
        #pragma unroll
        for (int i = 0; i < FIN_TPB / 32; ++i) { A += sa[i]; B += sb[i]; }
        double l_dd = A / ((double)BATCHN * (double)NX);
        double l_pi = B / ((double)BATCHN * (double)NTOT);
        out[0] = (float)(l_dd + 0.1 * l_pi);   // total_loss
        out[1] = (float)l_dd;
        out[2] = (float)l_pi;
    }
}

extern "C" void kernel_launch(void* const* d_in, const int* in_sizes, int n_in,
                              void* d_out, int out_size)
{
    const float* pred = (const float*)d_in[0];   // predictions [524288, 40]
    const float* targ = (const float*)d_in[1];   // targets     [524288, 40]
    const float* ycur = (const float*)d_in[2];   // y_current   [524288, 40]
    float* out = (float*)d_out;                  // [total, l_dd, l_pi]

    hybrid_loss_kernel<<<NBLOCKS, TPB>>>(pred, targ, ycur);
    finalize_kernel<<<FIN_GRID, FIN_TPB>>>(out);
}